// round 7
// baseline (speedup 1.0000x reference)
#include <cuda_runtime.h>
#include <cstdint>

#define SEQ 2048
#define DM  1024
#define DK  64
#define NB  8

// ------------------------- scratch (device globals) -------------------------
__device__ float g_Q[NB * SEQ * DK];                 //  4 MB
__device__ float g_K[NB * SEQ * DK];                 //  4 MB
__device__ float g_V[NB * SEQ * DM];                 // 64 MB
__device__ float g_S[(size_t)NB * SEQ * SEQ];        // 128 MB (scores -> P in place)
__device__ float g_Linv[NB * SEQ];

// ------------------------- helpers -------------------------
__device__ __forceinline__ uint32_t f2tf(float f) {
    uint32_t o;
    asm("cvt.rna.tf32.f32 %0, %1;" : "=r"(o) : "f"(f));
    return o;
}
__device__ __forceinline__ void mma_tf32(float* c, const uint32_t* a, const uint32_t* b) {
    asm volatile(
        "mma.sync.aligned.m16n8k8.row.col.f32.tf32.tf32.f32 "
        "{%0,%1,%2,%3}, {%4,%5,%6,%7}, {%8,%9}, {%0,%1,%2,%3};"
        : "+f"(c[0]), "+f"(c[1]), "+f"(c[2]), "+f"(c[3])
        : "r"(a[0]), "r"(a[1]), "r"(a[2]), "r"(a[3]), "r"(b[0]), "r"(b[1]));
}

// Fragment-order smem layouts.
// A fragment (m16k8): element (r',k') of 16x8 tile:
//   lane = (r'&7)*4 + (k'&3), reg = (r'>>3) | ((k'>>2)<<1)
// AF word index: frag(mt,ks) base = ((mt*2+ks)<<7), + swizzled_lane*4 + reg
// B fragment (k8n8): element (k',n'):
//   lane = n'*4 + (k'&3), reg = (k'>>2)
// BF word index: frag(nt,ks) base = ((nt*2+ks)<<6), + swizzled_lane*2 + reg
__device__ __forceinline__ int aswz(int sl, int ks) {
    return sl ^ ((ks << 2) | ((sl >> 3) & 3));
}
__device__ __forceinline__ int bswz(int sl, int nt, int ks) {
    return sl ^ ((nt & 15) ^ (ks << 1) ^ (((sl >> 4) & 1) * 5));
}

// ---------------------------------------------------------------------------
// tf32 mma.sync GEMM, fragment-order smem.
//   A: [M,K] row-major.
//   B: transB=0 -> [K,N] row-major;  transB=1 -> [N,K] row-major (B^T effective).
//   C = rowscale * (A @ B) + bias.  BM=128, BN=128, BK=16, 256 thr (4x2 warps).
//   causalK: K limited to (rb+1)*128.  causalSkip: skip block cols above diag.
// ---------------------------------------------------------------------------
__global__ __launch_bounds__(256, 2)
void mma_gemm(const float* __restrict__ A, const float* __restrict__ B,
              float* __restrict__ C, const float* __restrict__ bias,
              const float* __restrict__ rowscale,
              int N, int K, int transB, int causalK, int causalSkip,
              size_t sA, size_t sB, size_t sC, size_t sR)
{
    __shared__ uint32_t AF[2][16 * 128];   // 8KB per buf
    __shared__ uint32_t BF[2][32 * 64];    // 8KB per buf

    const int rb = blockIdx.y, cb = blockIdx.x, z = blockIdx.z;
    if (causalSkip && cb > rb) return;

    A += (size_t)z * sA;
    B += (size_t)z * sB;
    C += (size_t)z * sC;
    if (rowscale) rowscale += (size_t)z * sR;

    int kend = causalK ? (rb + 1) * 128 : K;
    if (kend > K) kend = K;
    const int NC = kend >> 4;

    const int tid = threadIdx.x, lane = tid & 31;
    const int wm = (tid >> 5) >> 1;      // 0..3
    const int wn = (tid >> 5) & 1;       // 0..1

    const float* Ab = A + (size_t)rb * 128 * K;

    float acc[2][8][4];
    #pragma unroll
    for (int i = 0; i < 2; i++)
        #pragma unroll
        for (int j = 0; j < 8; j++)
            #pragma unroll
            for (int q = 0; q < 4; q++) acc[i][j][q] = 0.f;

    float4 la[2], lb[2];

    auto gload = [&](int c) {
        const float* Ac = Ab + (c << 4);
        #pragma unroll
        for (int it = 0; it < 2; it++) {
            int f = tid + it * 256;
            la[it] = *reinterpret_cast<const float4*>(
                Ac + (size_t)(f >> 2) * K + ((f & 3) << 2));
        }
        if (!transB) {
            const float* Bc = B + (size_t)(c << 4) * N + cb * 128;
            #pragma unroll
            for (int it = 0; it < 2; it++) {
                int f = tid + it * 256;
                int kr = f >> 5, nc = (f & 31) << 2;
                if (cb * 128 + nc < N)
                    lb[it] = *reinterpret_cast<const float4*>(Bc + (size_t)kr * N + nc);
                else
                    lb[it] = make_float4(0.f, 0.f, 0.f, 0.f);
            }
        } else {
            const float* Bc = B + (size_t)(cb * 128) * K + (c << 4);
            #pragma unroll
            for (int it = 0; it < 2; it++) {
                int f = tid + it * 256;
                lb[it] = *reinterpret_cast<const float4*>(
                    Bc + (size_t)(f >> 2) * K + ((f & 3) << 2));
            }
        }
    };

    auto gstore = [&](int buf) {
        // A: thread covers (r, k0..k0+3)
        #pragma unroll
        for (int it = 0; it < 2; it++) {
            int f = tid + it * 256;
            int r = f >> 2, k0 = (f & 3) << 2;
            int mt = r >> 4, rp = r & 15, ks = k0 >> 3;
            int reg = ((rp >> 3) & 1) | (((k0 >> 2) & 1) << 1);
            int slb = (rp & 7) << 2;
            uint32_t* base = &AF[buf][((mt << 1) | ks) << 7];
            float v[4] = {la[it].x, la[it].y, la[it].z, la[it].w};
            #pragma unroll
            for (int i = 0; i < 4; i++) {
                int sl = slb + i;
                base[(aswz(sl, ks) << 2) | reg] = f2tf(v[i]);
            }
        }
        if (!transB) {
            // B: thread covers (kr, nc..nc+3)
            #pragma unroll
            for (int it = 0; it < 2; it++) {
                int f = tid + it * 256;
                int kr = f >> 5, nc = (f & 31) << 2;
                int ks = (kr >> 3) & 1, reg = (kr >> 2) & 1;
                float v[4] = {lb[it].x, lb[it].y, lb[it].z, lb[it].w};
                #pragma unroll
                for (int i = 0; i < 4; i++) {
                    int n = nc + i;
                    int nt = n >> 3;
                    int sl = ((n & 7) << 2) | (kr & 3);
                    BF[buf][(((nt << 1) | ks) << 6) | (bswz(sl, nt, ks) << 1) | reg] =
                        f2tf(v[i]);
                }
            }
        } else {
            // B^T: thread covers (nr, kc0..kc0+3)
            #pragma unroll
            for (int it = 0; it < 2; it++) {
                int f = tid + it * 256;
                int nr = f >> 2, kc0 = (f & 3) << 2;
                int nt = nr >> 3;
                int ks = (kc0 >> 3) & 1, reg = (kc0 >> 2) & 1;
                int slb = (nr & 7) << 2;
                float v[4] = {lb[it].x, lb[it].y, lb[it].z, lb[it].w};
                uint32_t* base = &BF[buf][((nt << 1) | ks) << 6];
                #pragma unroll
                for (int i = 0; i < 4; i++) {
                    int sl = slb | i;
                    base[(bswz(sl, nt, ks) << 1) | reg] = f2tf(v[i]);
                }
            }
        }
    };

    auto compute = [&](int buf) {
        #pragma unroll
        for (int ks = 0; ks < 2; ks++) {
            uint32_t a[2][4];
            #pragma unroll
            for (int mi = 0; mi < 2; mi++) {
                int mt = wm * 2 + mi;
                const uint4 v = *reinterpret_cast<const uint4*>(
                    &AF[buf][(((mt << 1) | ks) << 7) | (aswz(lane, ks) << 2)]);
                a[mi][0] = v.x; a[mi][1] = v.y; a[mi][2] = v.z; a[mi][3] = v.w;
            }
            uint32_t b[8][2];
            #pragma unroll
            for (int ni = 0; ni < 8; ni++) {
                int nt = wn * 8 + ni;
                const uint2 v = *reinterpret_cast<const uint2*>(
                    &BF[buf][(((nt << 1) | ks) << 6) | (bswz(lane, nt, ks) << 1)]);
                b[ni][0] = v.x; b[ni][1] = v.y;
            }
            #pragma unroll
            for (int mi = 0; mi < 2; mi++)
                #pragma unroll
                for (int ni = 0; ni < 8; ni++)
                    mma_tf32(acc[mi][ni], a[mi], b[ni]);
        }
    };

    gload(0);
    gstore(0);
    __syncthreads();
    for (int c = 0; c < NC; c++) {
        const int buf = c & 1;
        if (c + 1 < NC) gload(c + 1);
        compute(buf);
        if (c + 1 < NC) gstore(buf ^ 1);
        __syncthreads();
    }

    // ---------------- epilogue ----------------
    #pragma unroll
    for (int mi = 0; mi < 2; mi++) {
        int rbase = rb * 128 + wm * 32 + mi * 16 + (lane >> 2);
        #pragma unroll
        for (int half = 0; half < 2; half++) {
            int row = rbase + half * 8;
            float sc = rowscale ? rowscale[row] : 1.0f;
            float* Cp = C + (size_t)row * N;
            #pragma unroll
            for (int ni = 0; ni < 8; ni++) {
                int col = cb * 128 + wn * 64 + ni * 8 + ((lane & 3) << 1);
                if (col < N) {
                    float b0 = 0.f, b1 = 0.f;
                    if (bias) { b0 = bias[col]; b1 = bias[col + 1]; }
                    float2 o;
                    o.x = acc[mi][ni][half * 2 + 0] * sc + b0;
                    o.y = acc[mi][ni][half * 2 + 1] * sc + b1;
                    *reinterpret_cast<float2*>(Cp + col) = o;
                }
            }
        }
    }
}

// ---------------------------------------------------------------------------
// Rowwise causal softmax, in-place on S -> P. Writes Linv = 1/rowsum.
// Zero-fills cols [q+1, roundup(q+1,128)) so PV's 128-granular causal
// K-limit reads exact zeros above the diagonal.
// ---------------------------------------------------------------------------
__global__ __launch_bounds__(256)
void softmax_rows(float* __restrict__ S, float* __restrict__ Linv)
{
    __shared__ float red[256];
    const int q = blockIdx.x, b = blockIdx.y;
    float* row = S + ((size_t)b * SEQ + q) * SEQ;
    const int n = q + 1;
    const int nk4 = (((q >> 7) + 1) << 7) >> 2;
    const int tid = threadIdx.x;

    float m = -1e30f;
    for (int i = tid; i < nk4; i += 256) {
        float4 v = reinterpret_cast<const float4*>(row)[i];
        int base = i << 2;
        if (base + 0 < n) m = fmaxf(m, v.x);
        if (base + 1 < n) m = fmaxf(m, v.y);
        if (base + 2 < n) m = fmaxf(m, v.z);
        if (base + 3 < n) m = fmaxf(m, v.w);
    }
    red[tid] = m; __syncthreads();
    for (int s2 = 128; s2 > 0; s2 >>= 1) {
        if (tid < s2) red[tid] = fmaxf(red[tid], red[tid + s2]);
        __syncthreads();
    }
    m = red[0] * 0.125f;   // fold 1/sqrt(dk)
    __syncthreads();

    float sum = 0.f;
    for (int i = tid; i < nk4; i += 256) {
        float4 v = reinterpret_cast<const float4*>(row)[i];
        int base = i << 2;
        float4 p;
        p.x = (base + 0 < n) ? __expf(v.x * 0.125f - m) : 0.f;
        p.y = (base + 1 < n) ? __expf(v.y * 0.125f - m) : 0.f;
        p.z = (base + 2 < n) ? __expf(v.z * 0.125f - m) : 0.f;
        p.w = (base + 3 < n) ? __expf(v.w * 0.125f - m) : 0.f;
        sum += p.x + p.y + p.z + p.w;
        reinterpret_cast<float4*>(row)[i] = p;
    }
    red[tid] = sum; __syncthreads();
    for (int s2 = 128; s2 > 0; s2 >>= 1) {
        if (tid < s2) red[tid] += red[tid + s2];
        __syncthreads();
    }
    if (tid == 0) Linv[(size_t)b * SEQ + q] = 1.0f / red[0];
}

// ---------------------------------------------------------------------------
extern "C" void kernel_launch(void* const* d_in, const int* in_sizes, int n_in,
                              void* d_out, int out_size)
{
    const float* input = (const float*)d_in[0];
    const float* Wq = (const float*)d_in[1];
    const float* bq = (const float*)d_in[2];
    const float* Wk = (const float*)d_in[3];
    const float* bk = (const float*)d_in[4];
    const float* Wv = (const float*)d_in[5];
    const float* bv = (const float*)d_in[6];
    float* out = (float*)d_out;

    float *Q, *Kb, *V, *S, *L;
    cudaGetSymbolAddress((void**)&Q,  g_Q);
    cudaGetSymbolAddress((void**)&Kb, g_K);
    cudaGetSymbolAddress((void**)&V,  g_V);
    cudaGetSymbolAddress((void**)&S,  g_S);
    cudaGetSymbolAddress((void**)&L,  g_Linv);

    const int Mrows = NB * SEQ;   // 16384

    // Q = X @ Wq + bq            [16384, 64]     (B row-major [1024,64])
    mma_gemm<<<dim3(1, Mrows / 128, 1), 256>>>(
        input, Wq, Q, bq, nullptr, DK, DM, 0, 0, 0, 0, 0, 0, 0);
    // K = X @ Wk + bk
    mma_gemm<<<dim3(1, Mrows / 128, 1), 256>>>(
        input, Wk, Kb, bk, nullptr, DK, DM, 0, 0, 0, 0, 0, 0, 0);
    // V = X @ Wv + bv            [16384, 1024]
    mma_gemm<<<dim3(DM / 128, Mrows / 128, 1), 256>>>(
        input, Wv, V, bv, nullptr, DM, DM, 0, 0, 0, 0, 0, 0, 0);

    // S = Q @ K^T per batch (transB; blocks above diagonal skipped)
    mma_gemm<<<dim3(SEQ / 128, SEQ / 128, NB), 256>>>(
        Q, Kb, S, nullptr, nullptr, SEQ, DK, 1, 0, 1,
        (size_t)SEQ * DK, (size_t)SEQ * DK, (size_t)SEQ * SEQ, 0);

    // softmax rows: S -> P (in place) + Linv
    softmax_rows<<<dim3(SEQ, NB), 256>>>(S, L);

    // out = diag(Linv) * P @ V   (causal K-limit per 128-row block)
    mma_gemm<<<dim3(DM / 128, SEQ / 128, NB), 256>>>(
        S, V, out, nullptr, L, DM, SEQ, 0, 1, 0,
        (size_t)SEQ * SEQ, (size_t)SEQ * DM, (size_t)SEQ * DM, (size_t)SEQ);
}

// round 9
// speedup vs baseline: 1.1240x; 1.1240x over previous
#include <cuda_runtime.h>
#include <cstdint>

#define SEQ 2048
#define DM  1024
#define DK  64
#define NB  8

// ------------------------- scratch (device globals) -------------------------
__device__ float g_Q[NB * SEQ * DK];                 //  4 MB
__device__ float g_K[NB * SEQ * DK];                 //  4 MB
__device__ float g_V[NB * SEQ * DM];                 // 64 MB
__device__ float g_S[(size_t)NB * SEQ * SEQ];        // 128 MB (scores -> P in place)
__device__ float g_Linv[NB * SEQ];

// ------------------------- helpers -------------------------
__device__ __forceinline__ uint32_t f2tf(float f) {
    uint32_t o;
    asm("cvt.rna.tf32.f32 %0, %1;" : "=r"(o) : "f"(f));
    return o;
}
__device__ __forceinline__ void mma_tf32(float* c, const uint32_t* a, const uint32_t* b) {
    asm volatile(
        "mma.sync.aligned.m16n8k8.row.col.f32.tf32.tf32.f32 "
        "{%0,%1,%2,%3}, {%4,%5,%6,%7}, {%8,%9}, {%0,%1,%2,%3};"
        : "+f"(c[0]), "+f"(c[1]), "+f"(c[2]), "+f"(c[3])
        : "r"(a[0]), "r"(a[1]), "r"(a[2]), "r"(a[3]), "r"(b[0]), "r"(b[1]));
}
__device__ __forceinline__ void ldsm4(uint32_t& r0, uint32_t& r1, uint32_t& r2,
                                      uint32_t& r3, uint32_t addr) {
    asm volatile("ldmatrix.sync.aligned.m8n8.x4.shared.b16 {%0,%1,%2,%3}, [%4];"
        : "=r"(r0), "=r"(r1), "=r"(r2), "=r"(r3) : "r"(addr));
}

// Smem tile layout (both A and B^T): [128 rows][16 words], word index =
//   row*16 + ((chunk ^ ((row>>1)&3)) << 2) + (k&3),  chunk = k>>2.
// The chunk-XOR swizzle makes STS.128 stores AND ldmatrix reads conflict-free.

// ---------------------------------------------------------------------------
// tf32 mma.sync GEMM with ldmatrix fragment loads.
//   A: [M,K] row-major.
//   B: transB=0 -> [K,N] row-major;  transB=1 -> [N,K] row-major (B^T effective).
//   C = rowscale * (A @ B) + bias.  BM=128, BN=128, BK=16, 256 thr (4x2 warps).
//   causalK: K limited to (rb+1)*128.  causalSkip: skip block cols above diag.
// ---------------------------------------------------------------------------
__global__ __launch_bounds__(256, 2)
void mma_gemm(const float* __restrict__ A, const float* __restrict__ B,
              float* __restrict__ C, const float* __restrict__ bias,
              const float* __restrict__ rowscale,
              int N, int K, int transB, int causalK, int causalSkip,
              size_t sA, size_t sB, size_t sC, size_t sR)
{
    __shared__ uint32_t SM[8192];   // As[2] @ word 0 (2048 w/buf); Bs[2] @ word 4096

    const int rb = blockIdx.y, cb = blockIdx.x, z = blockIdx.z;
    if (causalSkip && cb > rb) return;

    A += (size_t)z * sA;
    B += (size_t)z * sB;
    C += (size_t)z * sC;
    if (rowscale) rowscale += (size_t)z * sR;

    int kend = causalK ? (rb + 1) * 128 : K;
    if (kend > K) kend = K;
    const int NC = kend >> 4;

    const int tid = threadIdx.x, lane = tid & 31;
    const int wm = (tid >> 5) >> 1;      // 0..3
    const int wn = (tid >> 5) & 1;       // 0..1

    const float* Ab = A + (size_t)rb * 128 * K;
    const uint32_t smb = (uint32_t)__cvta_generic_to_shared(SM);

    // ---- precompute ldmatrix addresses (buf 0); in-loop: +buf*8192B ----
    uint32_t adrA[2][2], adrB[4][2];
    {
        const int rA0 = wm * 32 + ((lane >> 3) & 1) * 8 + (lane & 7);
        const int clA = (lane >> 4) & 1;
        #pragma unroll
        for (int mi = 0; mi < 2; mi++) {
            int r = rA0 + mi * 16, s = (r >> 1) & 3;
            #pragma unroll
            for (int ks = 0; ks < 2; ks++) {
                int c = clA | (ks << 1);
                adrA[mi][ks] = smb + (uint32_t)(r * 16 + ((c ^ s) << 2)) * 4u;
            }
        }
        const int nB0 = wn * 64 + (lane & 7) + ((lane >> 4) & 1) * 8;
        const int clB = (lane >> 3) & 1;
        #pragma unroll
        for (int p = 0; p < 4; p++) {
            int n = nB0 + p * 16, s = (n >> 1) & 3;
            #pragma unroll
            for (int ks = 0; ks < 2; ks++) {
                int c = clB | (ks << 1);
                adrB[p][ks] = smb + (uint32_t)(4096 + n * 16 + ((c ^ s) << 2)) * 4u;
            }
        }
    }

    float acc[2][8][4];
    #pragma unroll
    for (int i = 0; i < 2; i++)
        #pragma unroll
        for (int j = 0; j < 8; j++)
            #pragma unroll
            for (int q = 0; q < 4; q++) acc[i][j][q] = 0.f;

    float4 la[2];
    float4 lb[2];
    float  lbs[2][4];

    auto gload = [&](int c) {
        const float* Ac = Ab + (c << 4);
        #pragma unroll
        for (int it = 0; it < 2; it++) {
            int f = tid + it * 256;
            la[it] = *reinterpret_cast<const float4*>(
                Ac + (size_t)(f >> 2) * K + ((f & 3) << 2));
        }
        if (!transB) {
            const float* Bc = B + (size_t)(c << 4) * N + cb * 128;
            #pragma unroll
            for (int it = 0; it < 2; it++) {
                int f = tid + it * 256;
                int n = f & 127, kc = f >> 7;
                bool ok = (cb * 128 + n) < N;
                #pragma unroll
                for (int i = 0; i < 4; i++)
                    lbs[it][i] = ok ? Bc[(size_t)(kc * 4 + i) * N + n] : 0.f;
            }
        } else {
            const float* Bc = B + (size_t)(cb * 128) * K + (c << 4);
            #pragma unroll
            for (int it = 0; it < 2; it++) {
                int f = tid + it * 256;
                lb[it] = *reinterpret_cast<const float4*>(
                    Bc + (size_t)(f >> 2) * K + ((f & 3) << 2));
            }
        }
    };

    auto gstore = [&](int buf) {
        uint32_t* AS = SM + buf * 2048;
        uint32_t* BS = SM + 4096 + buf * 2048;
        #pragma unroll
        for (int it = 0; it < 2; it++) {
            int f = tid + it * 256;
            int r = f >> 2, c = f & 3;
            uint32_t* p = AS + r * 16 + ((c ^ ((r >> 1) & 3)) << 2);
            uint4 o = {f2tf(la[it].x), f2tf(la[it].y), f2tf(la[it].z), f2tf(la[it].w)};
            *reinterpret_cast<uint4*>(p) = o;
        }
        if (!transB) {
            #pragma unroll
            for (int it = 0; it < 2; it++) {
                int f = tid + it * 256;
                int n = f & 127, c = f >> 7;
                uint32_t* p = BS + n * 16 + ((c ^ ((n >> 1) & 3)) << 2);
                uint4 o = {f2tf(lbs[it][0]), f2tf(lbs[it][1]),
                           f2tf(lbs[it][2]), f2tf(lbs[it][3])};
                *reinterpret_cast<uint4*>(p) = o;
            }
        } else {
            #pragma unroll
            for (int it = 0; it < 2; it++) {
                int f = tid + it * 256;
                int n = f >> 2, c = f & 3;
                uint32_t* p = BS + n * 16 + ((c ^ ((n >> 1) & 3)) << 2);
                uint4 o = {f2tf(lb[it].x), f2tf(lb[it].y), f2tf(lb[it].z), f2tf(lb[it].w)};
                *reinterpret_cast<uint4*>(p) = o;
            }
        }
    };

    auto compute = [&](int buf) {
        const uint32_t bo = (uint32_t)buf * 8192u;
        #pragma unroll
        for (int ks = 0; ks < 2; ks++) {
            uint32_t a[2][4], b[8][2];
            #pragma unroll
            for (int mi = 0; mi < 2; mi++)
                ldsm4(a[mi][0], a[mi][1], a[mi][2], a[mi][3], adrA[mi][ks] + bo);
            #pragma unroll
            for (int p = 0; p < 4; p++)
                ldsm4(b[2 * p][0], b[2 * p][1], b[2 * p + 1][0], b[2 * p + 1][1],
                      adrB[p][ks] + bo);
            #pragma unroll
            for (int mi = 0; mi < 2; mi++)
                #pragma unroll
                for (int ni = 0; ni < 8; ni++)
                    mma_tf32(acc[mi][ni], a[mi], b[ni]);
        }
    };

    gload(0);
    gstore(0);
    __syncthreads();
    for (int c = 0; c < NC; c++) {
        const int buf = c & 1;
        if (c + 1 < NC) gload(c + 1);
        compute(buf);
        if (c + 1 < NC) gstore(buf ^ 1);
        __syncthreads();
    }

    // ---------------- epilogue ----------------
    #pragma unroll
    for (int mi = 0; mi < 2; mi++) {
        int rbase = rb * 128 + wm * 32 + mi * 16 + (lane >> 2);
        #pragma unroll
        for (int half = 0; half < 2; half++) {
            int row = rbase + half * 8;
            float sc = rowscale ? rowscale[row] : 1.0f;
            float* Cp = C + (size_t)row * N;
            #pragma unroll
            for (int ni = 0; ni < 8; ni++) {
                int col = cb * 128 + wn * 64 + ni * 8 + ((lane & 3) << 1);
                if (col < N) {
                    float b0 = 0.f, b1 = 0.f;
                    if (bias) { b0 = bias[col]; b1 = bias[col + 1]; }
                    float2 o;
                    o.x = acc[mi][ni][half * 2 + 0] * sc + b0;
                    o.y = acc[mi][ni][half * 2 + 1] * sc + b1;
                    *reinterpret_cast<float2*>(Cp + col) = o;
                }
            }
        }
    }
}

// ---------------------------------------------------------------------------
// Rowwise causal softmax, in-place on S -> P. Writes Linv = 1/rowsum.
// Zero-fills cols [q+1, roundup(q+1,128)) so PV's 128-granular causal
// K-limit reads exact zeros above the diagonal.
// ---------------------------------------------------------------------------
__global__ __launch_bounds__(256)
void softmax_rows(float* __restrict__ S, float* __restrict__ Linv)
{
    __shared__ float red[256];
    const int q = blockIdx.x, b = blockIdx.y;
    float* row = S + ((size_t)b * SEQ + q) * SEQ;
    const int n = q + 1;
    const int nk4 = (((q >> 7) + 1) << 7) >> 2;
    const int tid = threadIdx.x;

    float m = -1e30f;
    for (int i = tid; i < nk4; i += 256) {
        float4 v = reinterpret_cast<const float4*>(row)[i];
        int base = i << 2;
        if (base + 0 < n) m = fmaxf(m, v.x);
        if (base + 1 < n) m = fmaxf(m, v.y);
        if (base + 2 < n) m = fmaxf(m, v.z);
        if (base + 3 < n) m = fmaxf(m, v.w);
    }
    red[tid] = m; __syncthreads();
    for (int s2 = 128; s2 > 0; s2 >>= 1) {
        if (tid < s2) red[tid] = fmaxf(red[tid], red[tid + s2]);
        __syncthreads();
    }
    m = red[0] * 0.125f;   // fold 1/sqrt(dk)
    __syncthreads();

    float sum = 0.f;
    for (int i = tid; i < nk4; i += 256) {
        float4 v = reinterpret_cast<const float4*>(row)[i];
        int base = i << 2;
        float4 p;
        p.x = (base + 0 < n) ? __expf(v.x * 0.125f - m) : 0.f;
        p.y = (base + 1 < n) ? __expf(v.y * 0.125f - m) : 0.f;
        p.z = (base + 2 < n) ? __expf(v.z * 0.125f - m) : 0.f;
        p.w = (base + 3 < n) ? __expf(v.w * 0.125f - m) : 0.f;
        sum += p.x + p.y + p.z + p.w;
        reinterpret_cast<float4*>(row)[i] = p;
    }
    red[tid] = sum; __syncthreads();
    for (int s2 = 128; s2 > 0; s2 >>= 1) {
        if (tid < s2) red[tid] += red[tid + s2];
        __syncthreads();
    }
    if (tid == 0) Linv[(size_t)b * SEQ + q] = 1.0f / red[0];
}

// ---------------------------------------------------------------------------
extern "C" void kernel_launch(void* const* d_in, const int* in_sizes, int n_in,
                              void* d_out, int out_size)
{
    const float* input = (const float*)d_in[0];
    const float* Wq = (const float*)d_in[1];
    const float* bq = (const float*)d_in[2];
    const float* Wk = (const float*)d_in[3];
    const float* bk = (const float*)d_in[4];
    const float* Wv = (const float*)d_in[5];
    const float* bv = (const float*)d_in[6];
    float* out = (float*)d_out;

    float *Q, *Kb, *V, *S, *L;
    cudaGetSymbolAddress((void**)&Q,  g_Q);
    cudaGetSymbolAddress((void**)&Kb, g_K);
    cudaGetSymbolAddress((void**)&V,  g_V);
    cudaGetSymbolAddress((void**)&S,  g_S);
    cudaGetSymbolAddress((void**)&L,  g_Linv);

    const int Mrows = NB * SEQ;   // 16384

    // Q = X @ Wq + bq            [16384, 64]     (B row-major [1024,64])
    mma_gemm<<<dim3(1, Mrows / 128, 1), 256>>>(
        input, Wq, Q, bq, nullptr, DK, DM, 0, 0, 0, 0, 0, 0, 0);
    // K = X @ Wk + bk
    mma_gemm<<<dim3(1, Mrows / 128, 1), 256>>>(
        input, Wk, Kb, bk, nullptr, DK, DM, 0, 0, 0, 0, 0, 0, 0);
    // V = X @ Wv + bv            [16384, 1024]
    mma_gemm<<<dim3(DM / 128, Mrows / 128, 1), 256>>>(
        input, Wv, V, bv, nullptr, DM, DM, 0, 0, 0, 0, 0, 0, 0);

    // S = Q @ K^T per batch (transB; blocks above diagonal skipped)
    mma_gemm<<<dim3(SEQ / 128, SEQ / 128, NB), 256>>>(
        Q, Kb, S, nullptr, nullptr, SEQ, DK, 1, 0, 1,
        (size_t)SEQ * DK, (size_t)SEQ * DK, (size_t)SEQ * SEQ, 0);

    // softmax rows: S -> P (in place) + Linv
    softmax_rows<<<dim3(SEQ, NB), 256>>>(S, L);

    // out = diag(Linv) * P @ V   (causal K-limit per 128-row block)
    mma_gemm<<<dim3(DM / 128, SEQ / 128, NB), 256>>>(
        S, V, out, nullptr, L, DM, SEQ, 0, 1, 0,
        (size_t)SEQ * SEQ, (size_t)SEQ * DM, (size_t)SEQ * DM, (size_t)SEQ);
}

// round 11
// speedup vs baseline: 1.6890x; 1.5026x over previous
#include <cuda_runtime.h>
#include <cstdint>

#define SEQ 2048
#define DM  1024
#define DK  64
#define NB  8

// ------------------------- scratch (device globals) -------------------------
__device__ float g_X [NB * SEQ * DM];                // 64 MB  (tf32-rounded input)
__device__ float g_QK[NB * SEQ * 128];               //  8 MB  (Q cols 0-63, K cols 64-127)
__device__ float g_V [NB * SEQ * DM];                // 64 MB
__device__ float g_VT[NB * DM * SEQ];                // 64 MB
__device__ float g_S [(size_t)NB * SEQ * SEQ];       // 128 MB (scores -> P in place)
__device__ float g_Linv[NB * SEQ];
__device__ float g_WqkT[128 * DM];                   // [Wq|Wk]^T, tf32
__device__ float g_WvT [DM * DM];                    // Wv^T, tf32
__device__ float g_bqk [128];

// ------------------------- helpers -------------------------
__device__ __forceinline__ uint32_t f2tf(float f) {
    uint32_t o;
    asm("cvt.rna.tf32.f32 %0, %1;" : "=r"(o) : "f"(f));
    return o;
}
__device__ __forceinline__ float f2tff(float f) { return __uint_as_float(f2tf(f)); }

__device__ __forceinline__ void mma_tf32(float* c, const uint32_t* a, const uint32_t* b) {
    asm volatile(
        "mma.sync.aligned.m16n8k8.row.col.f32.tf32.tf32.f32 "
        "{%0,%1,%2,%3}, {%4,%5,%6,%7}, {%8,%9}, {%0,%1,%2,%3};"
        : "+f"(c[0]), "+f"(c[1]), "+f"(c[2]), "+f"(c[3])
        : "r"(a[0]), "r"(a[1]), "r"(a[2]), "r"(a[3]), "r"(b[0]), "r"(b[1]));
}
__device__ __forceinline__ void ldsm4(uint32_t& r0, uint32_t& r1, uint32_t& r2,
                                      uint32_t& r3, uint32_t addr) {
    asm volatile("ldmatrix.sync.aligned.m8n8.x4.shared.b16 {%0,%1,%2,%3}, [%4];"
        : "=r"(r0), "=r"(r1), "=r"(r2), "=r"(r3) : "r"(addr));
}
__device__ __forceinline__ void cpasync16(uint32_t dst, uint64_t gsrc) {
    asm volatile("cp.async.cg.shared.global [%0], [%1], 16;" :: "r"(dst), "l"(gsrc) : "memory");
}
#define CP_COMMIT() asm volatile("cp.async.commit_group;" ::: "memory")
#define CP_WAIT2()  asm volatile("cp.async.wait_group 2;" ::: "memory")

// Smem tile layout (A and B identical): [128 rows][16 words], word index =
//   row*16 + ((chunk ^ ((row>>1)&3)) << 2) + (k&3),  chunk = k>>2.
// 16B cp.async dst slots and ldmatrix reads both conflict-free.

// ---------------------------------------------------------------------------
// tf32 mma.sync GEMM; operands PRE-ROUNDED to tf32 in gmem.
//   A: [M x K] rows lda.  B: [N x K] rows ldb (B^T effective).
//   C = rowscale * (A@B^T) + bias; optionally rounded to tf32 (outRound).
//   BM=128, BN=128, BK=16, 256 thr.  4-stage cp.async pipeline (64KB dyn smem).
// ---------------------------------------------------------------------------
__global__ __launch_bounds__(256, 2)
void mma_gemm(const float* __restrict__ A, const float* __restrict__ B,
              float* __restrict__ C, const float* __restrict__ bias,
              const float* __restrict__ rowscale,
              int N, int K, int lda, int ldb,
              int causalK, int causalSkip, int outRound,
              size_t sA, size_t sB, size_t sC, size_t sR)
{
    extern __shared__ uint32_t SM[];   // 4 stages x 16KB: A @ +0, B @ +8KB

    const int rb = blockIdx.y, cb = blockIdx.x, z = blockIdx.z;
    if (causalSkip && cb > rb) return;

    A += (size_t)z * sA;
    B += (size_t)z * sB;
    C += (size_t)z * sC;
    if (rowscale) rowscale += (size_t)z * sR;

    int kend = causalK ? (rb + 1) * 128 : K;
    if (kend > K) kend = K;
    const int NC = kend >> 4;

    const int tid = threadIdx.x, lane = tid & 31;
    const int wm = (tid >> 5) >> 1;      // 0..3
    const int wn = (tid >> 5) & 1;       // 0..1

    const float* Ab = A + (size_t)rb * 128 * lda;
    const float* Bb = B + (size_t)cb * 128 * ldb;
    uint64_t gAb, gBb;
    asm("cvta.to.global.u64 %0, %1;" : "=l"(gAb) : "l"(Ab));
    asm("cvta.to.global.u64 %0, %1;" : "=l"(gBb) : "l"(Bb));
    const uint32_t smb = (uint32_t)__cvta_generic_to_shared(SM);

    // per-thread cp.async slot precompute (2 A units + 2 B units per chunk)
    uint32_t dstA[2], dstB[2];
    uint64_t offA[2], offB[2];
    #pragma unroll
    for (int it = 0; it < 2; it++) {
        int f = tid + it * 256;
        int r = f >> 2, cc = f & 3;
        dstA[it] = smb + (uint32_t)(r * 16 + ((cc ^ ((r >> 1) & 3)) << 2)) * 4u;
        offA[it] = ((uint64_t)r * lda + (uint64_t)cc * 4) * 4u;
        dstB[it] = smb + 8192u + (uint32_t)(r * 16 + ((cc ^ ((r >> 1) & 3)) << 2)) * 4u;
        offB[it] = ((uint64_t)r * ldb + (uint64_t)cc * 4) * 4u;
    }

    // ldmatrix addresses (stage 0); in-loop: +stage*16384B
    uint32_t adrA[2][2], adrB[4][2];
    {
        const int rA0 = wm * 32 + ((lane >> 3) & 1) * 8 + (lane & 7);
        const int clA = (lane >> 4) & 1;
        #pragma unroll
        for (int mi = 0; mi < 2; mi++) {
            int r = rA0 + mi * 16, s = (r >> 1) & 3;
            #pragma unroll
            for (int ks = 0; ks < 2; ks++) {
                int c = clA | (ks << 1);
                adrA[mi][ks] = smb + (uint32_t)(r * 16 + ((c ^ s) << 2)) * 4u;
            }
        }
        const int nB0 = wn * 64 + (lane & 7) + ((lane >> 4) & 1) * 8;
        const int clB = (lane >> 3) & 1;
        #pragma unroll
        for (int p = 0; p < 4; p++) {
            int n = nB0 + p * 16, s = (n >> 1) & 3;
            #pragma unroll
            for (int ks = 0; ks < 2; ks++) {
                int c = clB | (ks << 1);
                adrB[p][ks] = smb + 8192u + (uint32_t)(n * 16 + ((c ^ s) << 2)) * 4u;
            }
        }
    }

    float acc[2][8][4];
    #pragma unroll
    for (int i = 0; i < 2; i++)
        #pragma unroll
        for (int j = 0; j < 8; j++)
            #pragma unroll
            for (int q = 0; q < 4; q++) acc[i][j][q] = 0.f;

    auto issue = [&](int c, int stg) {
        const uint32_t so = (uint32_t)stg * 16384u;
        const uint64_t co = (uint64_t)(c << 4) * 4u;
        #pragma unroll
        for (int it = 0; it < 2; it++)
            cpasync16(dstA[it] + so, gAb + co + offA[it]);
        #pragma unroll
        for (int it = 0; it < 2; it++)
            cpasync16(dstB[it] + so, gBb + co + offB[it]);
    };

    auto compute = [&](int stg) {
        const uint32_t bo = (uint32_t)stg * 16384u;
        #pragma unroll
        for (int ks = 0; ks < 2; ks++) {
            uint32_t a[2][4], b[8][2];
            #pragma unroll
            for (int mi = 0; mi < 2; mi++)
                ldsm4(a[mi][0], a[mi][1], a[mi][2], a[mi][3], adrA[mi][ks] + bo);
            #pragma unroll
            for (int p = 0; p < 4; p++)
                ldsm4(b[2 * p][0], b[2 * p][1], b[2 * p + 1][0], b[2 * p + 1][1],
                      adrB[p][ks] + bo);
            #pragma unroll
            for (int mi = 0; mi < 2; mi++)
                #pragma unroll
                for (int ni = 0; ni < 8; ni++)
                    mma_tf32(acc[mi][ni], a[mi], b[ni]);
        }
    };

    // 4-stage pipeline
    #pragma unroll
    for (int s = 0; s < 3; s++) {
        if (s < NC) issue(s, s);
        CP_COMMIT();
    }
    for (int c = 0; c < NC; c++) {
        CP_WAIT2();
        __syncthreads();
        compute(c & 3);
        const int nc = c + 3;
        if (nc < NC) issue(nc, nc & 3);
        CP_COMMIT();
    }

    // ---------------- epilogue ----------------
    #pragma unroll
    for (int mi = 0; mi < 2; mi++) {
        int rbase = rb * 128 + wm * 32 + mi * 16 + (lane >> 2);
        #pragma unroll
        for (int half = 0; half < 2; half++) {
            int row = rbase + half * 8;
            float sc = rowscale ? rowscale[row] : 1.0f;
            float* Cp = C + (size_t)row * N;
            #pragma unroll
            for (int ni = 0; ni < 8; ni++) {
                int col = cb * 128 + wn * 64 + ni * 8 + ((lane & 3) << 1);
                float b0 = 0.f, b1 = 0.f;
                if (bias) { b0 = bias[col]; b1 = bias[col + 1]; }
                float2 o;
                o.x = acc[mi][ni][half * 2 + 0] * sc + b0;
                o.y = acc[mi][ni][half * 2 + 1] * sc + b1;
                if (outRound) { o.x = f2tff(o.x); o.y = f2tff(o.y); }
                *reinterpret_cast<float2*>(Cp + col) = o;
            }
        }
    }
}

// ---------------------------------------------------------------------------
// elementwise tf32 rounding (for the input X)
// ---------------------------------------------------------------------------
__global__ void conv_tf32(const float4* __restrict__ in, float4* __restrict__ out, int n4)
{
    int i = blockIdx.x * blockDim.x + threadIdx.x;
    if (i < n4) {
        float4 v = in[i];
        out[i] = make_float4(f2tff(v.x), f2tff(v.y), f2tff(v.z), f2tff(v.w));
    }
}

// ---------------------------------------------------------------------------
// 32x32 tiled transpose with tf32 rounding (idempotent). out[c][r] = tf32(in[r][c]).
// ---------------------------------------------------------------------------
__global__ void transpose_tf32(const float* __restrict__ in, float* __restrict__ out,
                               int R, int C, size_t sIn, size_t sOut)
{
    __shared__ float t[32][33];
    in  += (size_t)blockIdx.z * sIn;
    out += (size_t)blockIdx.z * sOut;
    int c0 = blockIdx.x * 32, r0 = blockIdx.y * 32;
    int tx = threadIdx.x, ty = threadIdx.y;
    #pragma unroll
    for (int i = 0; i < 32; i += 8)
        t[ty + i][tx] = in[(size_t)(r0 + ty + i) * C + (c0 + tx)];
    __syncthreads();
    #pragma unroll
    for (int i = 0; i < 32; i += 8)
        out[(size_t)(c0 + ty + i) * R + (r0 + tx)] = f2tff(t[tx][ty + i]);
}

__global__ void concat_bias(const float* __restrict__ bq, const float* __restrict__ bk,
                            float* __restrict__ o)
{
    int t = threadIdx.x;
    o[t] = (t < 64) ? bq[t] : bk[t - 64];
}

// ---------------------------------------------------------------------------
// Rowwise causal softmax, in-place on S -> P (tf32-rounded). Linv = 1/rowsum.
// Zero-fills cols [q+1, roundup(q+1,128)).
// ---------------------------------------------------------------------------
__global__ __launch_bounds__(256)
void softmax_rows(float* __restrict__ S, float* __restrict__ Linv)
{
    __shared__ float red[256];
    const int q = blockIdx.x, b = blockIdx.y;
    float* row = S + ((size_t)b * SEQ + q) * SEQ;
    const int n = q + 1;
    const int nk4 = (((q >> 7) + 1) << 7) >> 2;
    const int tid = threadIdx.x;

    float m = -1e30f;
    for (int i = tid; i < nk4; i += 256) {
        float4 v = reinterpret_cast<const float4*>(row)[i];
        int base = i << 2;
        if (base + 0 < n) m = fmaxf(m, v.x);
        if (base + 1 < n) m = fmaxf(m, v.y);
        if (base + 2 < n) m = fmaxf(m, v.z);
        if (base + 3 < n) m = fmaxf(m, v.w);
    }
    red[tid] = m; __syncthreads();
    for (int s2 = 128; s2 > 0; s2 >>= 1) {
        if (tid < s2) red[tid] = fmaxf(red[tid], red[tid + s2]);
        __syncthreads();
    }
    m = red[0] * 0.125f;   // fold 1/sqrt(dk)
    __syncthreads();

    float sum = 0.f;
    for (int i = tid; i < nk4; i += 256) {
        float4 v = reinterpret_cast<const float4*>(row)[i];
        int base = i << 2;
        float4 p;
        p.x = (base + 0 < n) ? __expf(v.x * 0.125f - m) : 0.f;
        p.y = (base + 1 < n) ? __expf(v.y * 0.125f - m) : 0.f;
        p.z = (base + 2 < n) ? __expf(v.z * 0.125f - m) : 0.f;
        p.w = (base + 3 < n) ? __expf(v.w * 0.125f - m) : 0.f;
        sum += p.x + p.y + p.z + p.w;
        p.x = f2tff(p.x); p.y = f2tff(p.y); p.z = f2tff(p.z); p.w = f2tff(p.w);
        reinterpret_cast<float4*>(row)[i] = p;
    }
    red[tid] = sum; __syncthreads();
    for (int s2 = 128; s2 > 0; s2 >>= 1) {
        if (tid < s2) red[tid] += red[tid + s2];
        __syncthreads();
    }
    if (tid == 0) Linv[(size_t)b * SEQ + q] = 1.0f / red[0];
}

// ---------------------------------------------------------------------------
extern "C" void kernel_launch(void* const* d_in, const int* in_sizes, int n_in,
                              void* d_out, int out_size)
{
    const float* input = (const float*)d_in[0];
    const float* Wq = (const float*)d_in[1];
    const float* bq = (const float*)d_in[2];
    const float* Wk = (const float*)d_in[3];
    const float* bk = (const float*)d_in[4];
    const float* Wv = (const float*)d_in[5];
    const float* bv = (const float*)d_in[6];
    float* out = (float*)d_out;

    float *X, *QK, *V, *VT, *S, *L, *WqkT, *WvT, *bqk;
    cudaGetSymbolAddress((void**)&X,    g_X);
    cudaGetSymbolAddress((void**)&QK,   g_QK);
    cudaGetSymbolAddress((void**)&V,    g_V);
    cudaGetSymbolAddress((void**)&VT,   g_VT);
    cudaGetSymbolAddress((void**)&S,    g_S);
    cudaGetSymbolAddress((void**)&L,    g_Linv);
    cudaGetSymbolAddress((void**)&WqkT, g_WqkT);
    cudaGetSymbolAddress((void**)&WvT,  g_WvT);
    cudaGetSymbolAddress((void**)&bqk,  g_bqk);

    static int attrDone = 0;
    if (!attrDone) {
        cudaFuncSetAttribute(mma_gemm, cudaFuncAttributeMaxDynamicSharedMemorySize, 65536);
        attrDone = 1;
    }
    const int SMEMB = 65536;
    const int Mrows = NB * SEQ;   // 16384
    dim3 tb(32, 8);

    // pre-passes: round X; transpose+round weights; concat bias
    conv_tf32<<<Mrows * DM / 4 / 256, 256>>>(
        (const float4*)input, (float4*)X, Mrows * DM / 4);
    transpose_tf32<<<dim3(2, 32), tb>>>(Wq, WqkT, DM, DK, 0, 0);
    transpose_tf32<<<dim3(2, 32), tb>>>(Wk, WqkT + 64 * DM, DM, DK, 0, 0);
    transpose_tf32<<<dim3(32, 32), tb>>>(Wv, WvT, DM, DM, 0, 0);
    concat_bias<<<1, 128>>>(bq, bk, bqk);

    // QK = X @ [Wq|Wk] + [bq|bk]   [16384, 128], tf32-rounded out
    mma_gemm<<<dim3(1, Mrows / 128), 256, SMEMB>>>(
        X, WqkT, QK, bqk, nullptr, 128, DM, DM, DM, 0, 0, 1, 0, 0, 0, 0);

    // V = X @ Wv + bv   [16384, 1024], tf32-rounded out
    mma_gemm<<<dim3(DM / 128, Mrows / 128), 256, SMEMB>>>(
        X, WvT, V, bv, nullptr, DM, DM, DM, DM, 0, 0, 1, 0, 0, 0, 0);

    // S = Q @ K^T per batch (block-causal skip)
    mma_gemm<<<dim3(SEQ / 128, SEQ / 128, NB), 256, SMEMB>>>(
        QK, QK + 64, S, nullptr, nullptr, SEQ, DK, 128, 128, 0, 1, 0,
        (size_t)SEQ * 128, (size_t)SEQ * 128, (size_t)SEQ * SEQ, 0);

    // softmax rows: S -> P (tf32) + Linv
    softmax_rows<<<dim3(SEQ, NB), 256>>>(S, L);

    // VT = V^T per batch [1024, 2048] (bits already tf32)
    transpose_tf32<<<dim3(DM / 32, SEQ / 32, NB), tb>>>(
        V, VT, SEQ, DM, (size_t)SEQ * DM, (size_t)SEQ * DM);

    // out = diag(Linv) * P @ V   (causal K-limit)
    mma_gemm<<<dim3(DM / 128, SEQ / 128, NB), 256, SMEMB>>>(
        S, VT, out, nullptr, L, DM, SEQ, SEQ, SEQ, 1, 0, 0,
        (size_t)SEQ * SEQ, (size_t)DM * SEQ, (size_t)SEQ * DM, (size_t)SEQ);
}

// round 12
// speedup vs baseline: 1.8379x; 1.0882x over previous
#include <cuda_runtime.h>
#include <cstdint>

#define SEQ 2048
#define DM  1024
#define DK  64
#define NB  8

// ------------------------- scratch (device globals) -------------------------
__device__ float g_X [NB * SEQ * DM];                // 64 MB  (tf32-rounded input)
__device__ float g_QK[NB * SEQ * 128];               //  8 MB  (Q cols 0-63, K cols 64-127)
__device__ float g_V [NB * SEQ * DM];                // 64 MB
__device__ float g_VT[NB * DM * SEQ];                // 64 MB
__device__ float g_S [(size_t)NB * SEQ * SEQ];       // 128 MB (P, written once)
__device__ float g_Lpart[NB * SEQ * 16];             //  1 MB  (per-cb row partial sums)
__device__ float g_Linv[NB * SEQ];
__device__ float g_WqkT[128 * DM];                   // [Wq|Wk]^T, tf32
__device__ float g_WvT [DM * DM];                    // Wv^T, tf32
__device__ float g_bqk [128];

// ------------------------- helpers -------------------------
__device__ __forceinline__ uint32_t f2tf(float f) {
    uint32_t o;
    asm("cvt.rna.tf32.f32 %0, %1;" : "=r"(o) : "f"(f));
    return o;
}
__device__ __forceinline__ float f2tff(float f) { return __uint_as_float(f2tf(f)); }

__device__ __forceinline__ void mma_tf32(float* c, const uint32_t* a, const uint32_t* b) {
    asm volatile(
        "mma.sync.aligned.m16n8k8.row.col.f32.tf32.tf32.f32 "
        "{%0,%1,%2,%3}, {%4,%5,%6,%7}, {%8,%9}, {%0,%1,%2,%3};"
        : "+f"(c[0]), "+f"(c[1]), "+f"(c[2]), "+f"(c[3])
        : "r"(a[0]), "r"(a[1]), "r"(a[2]), "r"(a[3]), "r"(b[0]), "r"(b[1]));
}
__device__ __forceinline__ void ldsm4(uint32_t& r0, uint32_t& r1, uint32_t& r2,
                                      uint32_t& r3, uint32_t addr) {
    asm volatile("ldmatrix.sync.aligned.m8n8.x4.shared.b16 {%0,%1,%2,%3}, [%4];"
        : "=r"(r0), "=r"(r1), "=r"(r2), "=r"(r3) : "r"(addr));
}
__device__ __forceinline__ void cpasync16(uint32_t dst, uint64_t gsrc) {
    asm volatile("cp.async.cg.shared.global [%0], [%1], 16;" :: "r"(dst), "l"(gsrc) : "memory");
}
#define CP_COMMIT() asm volatile("cp.async.commit_group;" ::: "memory")
#define CP_WAIT2()  asm volatile("cp.async.wait_group 2;" ::: "memory")

// Smem tile layout (A and B identical): [128 rows][16 words], word index =
//   row*16 + ((chunk ^ ((row>>1)&3)) << 2) + (k&3),  chunk = k>>2.

// ---------------------------------------------------------------------------
// tf32 mma.sync GEMM; operands PRE-ROUNDED to tf32 in gmem.
//   A: [M x K] rows lda.  B: [N x K] rows ldb (B^T effective).
//   normal: C = rowscale * (A@B^T) + bias (outRound optional)
//   scoreExp: C = tf32(exp(acc/8)) with causal diag mask; row partials -> lpart
// ---------------------------------------------------------------------------
__global__ __launch_bounds__(256, 2)
void mma_gemm(const float* __restrict__ A, const float* __restrict__ B,
              float* __restrict__ C, const float* __restrict__ bias,
              const float* __restrict__ rowscale, float* __restrict__ lpart,
              int N, int K, int lda, int ldb,
              int causalK, int causalSkip, int outRound, int scoreExp,
              size_t sA, size_t sB, size_t sC, size_t sR)
{
    extern __shared__ uint32_t SM[];   // 4 stages x 16KB: A @ +0, B @ +8KB

    const int rb = blockIdx.y, cb = blockIdx.x, z = blockIdx.z;
    if (causalSkip && cb > rb) return;

    A += (size_t)z * sA;
    B += (size_t)z * sB;
    C += (size_t)z * sC;
    if (rowscale) rowscale += (size_t)z * sR;

    int kend = causalK ? (rb + 1) * 128 : K;
    if (kend > K) kend = K;
    const int NC = kend >> 4;

    const int tid = threadIdx.x, lane = tid & 31;
    const int wm = (tid >> 5) >> 1;      // 0..3
    const int wn = (tid >> 5) & 1;       // 0..1

    const float* Ab = A + (size_t)rb * 128 * lda;
    const float* Bb = B + (size_t)cb * 128 * ldb;
    uint64_t gAb, gBb;
    asm("cvta.to.global.u64 %0, %1;" : "=l"(gAb) : "l"(Ab));
    asm("cvta.to.global.u64 %0, %1;" : "=l"(gBb) : "l"(Bb));
    const uint32_t smb = (uint32_t)__cvta_generic_to_shared(SM);

    uint32_t dstA[2], dstB[2];
    uint64_t offA[2], offB[2];
    #pragma unroll
    for (int it = 0; it < 2; it++) {
        int f = tid + it * 256;
        int r = f >> 2, cc = f & 3;
        dstA[it] = smb + (uint32_t)(r * 16 + ((cc ^ ((r >> 1) & 3)) << 2)) * 4u;
        offA[it] = ((uint64_t)r * lda + (uint64_t)cc * 4) * 4u;
        dstB[it] = smb + 8192u + (uint32_t)(r * 16 + ((cc ^ ((r >> 1) & 3)) << 2)) * 4u;
        offB[it] = ((uint64_t)r * ldb + (uint64_t)cc * 4) * 4u;
    }

    uint32_t adrA[2][2], adrB[4][2];
    {
        const int rA0 = wm * 32 + ((lane >> 3) & 1) * 8 + (lane & 7);
        const int clA = (lane >> 4) & 1;
        #pragma unroll
        for (int mi = 0; mi < 2; mi++) {
            int r = rA0 + mi * 16, s = (r >> 1) & 3;
            #pragma unroll
            for (int ks = 0; ks < 2; ks++) {
                int c = clA | (ks << 1);
                adrA[mi][ks] = smb + (uint32_t)(r * 16 + ((c ^ s) << 2)) * 4u;
            }
        }
        const int nB0 = wn * 64 + (lane & 7) + ((lane >> 4) & 1) * 8;
        const int clB = (lane >> 3) & 1;
        #pragma unroll
        for (int p = 0; p < 4; p++) {
            int n = nB0 + p * 16, s = (n >> 1) & 3;
            #pragma unroll
            for (int ks = 0; ks < 2; ks++) {
                int c = clB | (ks << 1);
                adrB[p][ks] = smb + 8192u + (uint32_t)(n * 16 + ((c ^ s) << 2)) * 4u;
            }
        }
    }

    float acc[2][8][4];
    #pragma unroll
    for (int i = 0; i < 2; i++)
        #pragma unroll
        for (int j = 0; j < 8; j++)
            #pragma unroll
            for (int q = 0; q < 4; q++) acc[i][j][q] = 0.f;

    auto issue = [&](int c, int stg) {
        const uint32_t so = (uint32_t)stg * 16384u;
        const uint64_t co = (uint64_t)(c << 4) * 4u;
        #pragma unroll
        for (int it = 0; it < 2; it++)
            cpasync16(dstA[it] + so, gAb + co + offA[it]);
        #pragma unroll
        for (int it = 0; it < 2; it++)
            cpasync16(dstB[it] + so, gBb + co + offB[it]);
    };

    auto compute = [&](int stg) {
        const uint32_t bo = (uint32_t)stg * 16384u;
        #pragma unroll
        for (int ks = 0; ks < 2; ks++) {
            uint32_t a[2][4], b[8][2];
            #pragma unroll
            for (int mi = 0; mi < 2; mi++)
                ldsm4(a[mi][0], a[mi][1], a[mi][2], a[mi][3], adrA[mi][ks] + bo);
            #pragma unroll
            for (int p = 0; p < 4; p++)
                ldsm4(b[2 * p][0], b[2 * p][1], b[2 * p + 1][0], b[2 * p + 1][1],
                      adrB[p][ks] + bo);
            #pragma unroll
            for (int mi = 0; mi < 2; mi++)
                #pragma unroll
                for (int ni = 0; ni < 8; ni++)
                    mma_tf32(acc[mi][ni], a[mi], b[ni]);
        }
    };

    #pragma unroll
    for (int s = 0; s < 3; s++) {
        if (s < NC) issue(s, s);
        CP_COMMIT();
    }
    for (int c = 0; c < NC; c++) {
        CP_WAIT2();
        __syncthreads();
        compute(c & 3);
        const int nc = c + 3;
        if (nc < NC) issue(nc, nc & 3);
        CP_COMMIT();
    }

    // ---------------- epilogue ----------------
    if (scoreExp) {
        // P = tf32(exp(acc/8)), diag mask; per-row partial sums -> lpart
        const bool diag = (cb == rb);
        float part[2][2] = {{0.f, 0.f}, {0.f, 0.f}};
        #pragma unroll
        for (int mi = 0; mi < 2; mi++) {
            int rbase = rb * 128 + wm * 32 + mi * 16 + (lane >> 2);
            #pragma unroll
            for (int half = 0; half < 2; half++) {
                int row = rbase + half * 8;
                float* Cp = C + (size_t)row * N;
                #pragma unroll
                for (int ni = 0; ni < 8; ni++) {
                    int col = cb * 128 + wn * 64 + ni * 8 + ((lane & 3) << 1);
                    float e0 = __expf(acc[mi][ni][half * 2 + 0] * 0.125f);
                    float e1 = __expf(acc[mi][ni][half * 2 + 1] * 0.125f);
                    if (diag) {
                        if (col > row) e0 = 0.f;
                        if (col + 1 > row) e1 = 0.f;
                    }
                    part[mi][half] += e0 + e1;
                    float2 o = {f2tff(e0), f2tff(e1)};
                    *reinterpret_cast<float2*>(Cp + col) = o;
                }
            }
        }
        __syncthreads();                 // smem pipeline no longer needed
        float* rs = reinterpret_cast<float*>(SM);   // [128][2]
        #pragma unroll
        for (int mi = 0; mi < 2; mi++)
            #pragma unroll
            for (int half = 0; half < 2; half++) {
                float v = part[mi][half];
                v += __shfl_xor_sync(0xFFFFFFFF, v, 1);
                v += __shfl_xor_sync(0xFFFFFFFF, v, 2);
                if ((lane & 3) == 0) {
                    int rl = wm * 32 + mi * 16 + half * 8 + (lane >> 2);
                    rs[rl * 2 + wn] = v;
                }
            }
        __syncthreads();
        if (tid < 128)
            lpart[(((size_t)z * SEQ) + rb * 128 + tid) * 16 + cb] =
                rs[tid * 2] + rs[tid * 2 + 1];
        return;
    }

    #pragma unroll
    for (int mi = 0; mi < 2; mi++) {
        int rbase = rb * 128 + wm * 32 + mi * 16 + (lane >> 2);
        #pragma unroll
        for (int half = 0; half < 2; half++) {
            int row = rbase + half * 8;
            float sc = rowscale ? rowscale[row] : 1.0f;
            float* Cp = C + (size_t)row * N;
            #pragma unroll
            for (int ni = 0; ni < 8; ni++) {
                int col = cb * 128 + wn * 64 + ni * 8 + ((lane & 3) << 1);
                float b0 = 0.f, b1 = 0.f;
                if (bias) { b0 = bias[col]; b1 = bias[col + 1]; }
                float2 o;
                o.x = acc[mi][ni][half * 2 + 0] * sc + b0;
                o.y = acc[mi][ni][half * 2 + 1] * sc + b1;
                if (outRound) { o.x = f2tff(o.x); o.y = f2tff(o.y); }
                *reinterpret_cast<float2*>(Cp + col) = o;
            }
        }
    }
}

// ---------------------------------------------------------------------------
__global__ void conv_tf32(const float4* __restrict__ in, float4* __restrict__ out, int n4)
{
    int i = blockIdx.x * blockDim.x + threadIdx.x;
    if (i < n4) {
        float4 v = in[i];
        out[i] = make_float4(f2tff(v.x), f2tff(v.y), f2tff(v.z), f2tff(v.w));
    }
}

__global__ void transpose_tf32(const float* __restrict__ in, float* __restrict__ out,
                               int R, int C, size_t sIn, size_t sOut)
{
    __shared__ float t[32][33];
    in  += (size_t)blockIdx.z * sIn;
    out += (size_t)blockIdx.z * sOut;
    int c0 = blockIdx.x * 32, r0 = blockIdx.y * 32;
    int tx = threadIdx.x, ty = threadIdx.y;
    #pragma unroll
    for (int i = 0; i < 32; i += 8)
        t[ty + i][tx] = in[(size_t)(r0 + ty + i) * C + (c0 + tx)];
    __syncthreads();
    #pragma unroll
    for (int i = 0; i < 32; i += 8)
        out[(size_t)(c0 + ty + i) * R + (r0 + tx)] = f2tff(t[tx][ty + i]);
}

__global__ void concat_bias(const float* __restrict__ bq, const float* __restrict__ bk,
                            float* __restrict__ o)
{
    int t = threadIdx.x;
    o[t] = (t < 64) ? bq[t] : bk[t - 64];
}

// Linv[b][q] = 1 / sum_{cb<=q/128} Lpart[b][q][cb]   (fixed order: deterministic)
__global__ void linv_reduce(const float* __restrict__ lpart, float* __restrict__ linv)
{
    int i = blockIdx.x * blockDim.x + threadIdx.x;   // 0 .. NB*SEQ-1
    if (i < NB * SEQ) {
        int q = i & (SEQ - 1);
        int nb = (q >> 7) + 1;
        const float* p = lpart + (size_t)i * 16;
        float s = 0.f;
        for (int c = 0; c < nb; c++) s += p[c];
        linv[i] = 1.0f / s;
    }
}

// ---------------------------------------------------------------------------
extern "C" void kernel_launch(void* const* d_in, const int* in_sizes, int n_in,
                              void* d_out, int out_size)
{
    const float* input = (const float*)d_in[0];
    const float* Wq = (const float*)d_in[1];
    const float* bq = (const float*)d_in[2];
    const float* Wk = (const float*)d_in[3];
    const float* bk = (const float*)d_in[4];
    const float* Wv = (const float*)d_in[5];
    const float* bv = (const float*)d_in[6];
    float* out = (float*)d_out;

    float *X, *QK, *V, *VT, *S, *Lp, *L, *WqkT, *WvT, *bqk;
    cudaGetSymbolAddress((void**)&X,    g_X);
    cudaGetSymbolAddress((void**)&QK,   g_QK);
    cudaGetSymbolAddress((void**)&V,    g_V);
    cudaGetSymbolAddress((void**)&VT,   g_VT);
    cudaGetSymbolAddress((void**)&S,    g_S);
    cudaGetSymbolAddress((void**)&Lp,   g_Lpart);
    cudaGetSymbolAddress((void**)&L,    g_Linv);
    cudaGetSymbolAddress((void**)&WqkT, g_WqkT);
    cudaGetSymbolAddress((void**)&WvT,  g_WvT);
    cudaGetSymbolAddress((void**)&bqk,  g_bqk);

    static int attrDone = 0;
    if (!attrDone) {
        cudaFuncSetAttribute(mma_gemm, cudaFuncAttributeMaxDynamicSharedMemorySize, 65536);
        attrDone = 1;
    }
    const int SMEMB = 65536;
    const int Mrows = NB * SEQ;   // 16384
    dim3 tb(32, 8);

    // pre-passes
    conv_tf32<<<Mrows * DM / 4 / 256, 256>>>(
        (const float4*)input, (float4*)X, Mrows * DM / 4);
    transpose_tf32<<<dim3(2, 32), tb>>>(Wq, WqkT, DM, DK, 0, 0);
    transpose_tf32<<<dim3(2, 32), tb>>>(Wk, WqkT + 64 * DM, DM, DK, 0, 0);
    transpose_tf32<<<dim3(32, 32), tb>>>(Wv, WvT, DM, DM, 0, 0);
    concat_bias<<<1, 128>>>(bq, bk, bqk);

    // QK = X @ [Wq|Wk] + [bq|bk]  (tf32-rounded out)
    mma_gemm<<<dim3(1, Mrows / 128), 256, SMEMB>>>(
        X, WqkT, QK, bqk, nullptr, nullptr, 128, DM, DM, DM, 0, 0, 1, 0, 0, 0, 0, 0);

    // V = X @ Wv + bv  (tf32-rounded out)
    mma_gemm<<<dim3(DM / 128, Mrows / 128), 256, SMEMB>>>(
        X, WvT, V, bv, nullptr, nullptr, DM, DM, DM, DM, 0, 0, 1, 0, 0, 0, 0, 0);

    // P = tf32(exp(Q@K^T / 8)) with diag mask; row partials -> Lpart
    mma_gemm<<<dim3(SEQ / 128, SEQ / 128, NB), 256, SMEMB>>>(
        QK, QK + 64, S, nullptr, nullptr, Lp, SEQ, DK, 128, 128, 0, 1, 0, 1,
        (size_t)SEQ * 128, (size_t)SEQ * 128, (size_t)SEQ * SEQ, 0);

    // Linv = 1 / rowsum
    linv_reduce<<<Mrows / 256, 256>>>(Lp, L);

    // VT = V^T per batch
    transpose_tf32<<<dim3(DM / 32, SEQ / 32, NB), tb>>>(
        V, VT, SEQ, DM, (size_t)SEQ * DM, (size_t)SEQ * DM);

    // out = diag(Linv) * P @ V
    mma_gemm<<<dim3(DM / 128, SEQ / 128, NB), 256, SMEMB>>>(
        S, VT, out, nullptr, L, nullptr, DM, SEQ, SEQ, SEQ, 1, 0, 0, 0,
        (size_t)SEQ * SEQ, (size_t)DM * SEQ, (size_t)SEQ * DM, (size_t)SEQ);
}

// round 13
// speedup vs baseline: 2.9394x; 1.5994x over previous
#include <cuda_runtime.h>
#include <cuda_fp16.h>
#include <cstdint>

#define SEQ 2048
#define DM  1024
#define DK  64
#define NB  8

// ------------------------- scratch (device globals) -------------------------
__device__ __half g_Xh [NB * SEQ * DM];               // 32 MB (fp16 input)
__device__ __half g_QKh[NB * SEQ * 128];              //  4 MB (Q cols 0-63, K cols 64-127)
__device__ __half g_VTh[NB * DM * SEQ];               // 32 MB (V^T per batch)
__device__ __half g_Ph [(size_t)NB * SEQ * SEQ];      // 64 MB (P = exp(S/8), masked)
__device__ float  g_Lpart[NB * SEQ * 16];             //  1 MB
__device__ float  g_Linv[NB * SEQ];
__device__ __half g_WqkTh[128 * DM];                  // [Wq|Wk]^T fp16
__device__ __half g_WvTh [DM * DM];                   // Wv^T fp16
__device__ float  g_bqk  [128];

// ------------------------- helpers -------------------------
__device__ __forceinline__ void mma_f16(float* c, const uint32_t* a, const uint32_t* b) {
    asm volatile(
        "mma.sync.aligned.m16n8k16.row.col.f32.f16.f16.f32 "
        "{%0,%1,%2,%3}, {%4,%5,%6,%7}, {%8,%9}, {%0,%1,%2,%3};"
        : "+f"(c[0]), "+f"(c[1]), "+f"(c[2]), "+f"(c[3])
        : "r"(a[0]), "r"(a[1]), "r"(a[2]), "r"(a[3]), "r"(b[0]), "r"(b[1]));
}
__device__ __forceinline__ void ldsm4(uint32_t& r0, uint32_t& r1, uint32_t& r2,
                                      uint32_t& r3, uint32_t addr) {
    asm volatile("ldmatrix.sync.aligned.m8n8.x4.shared.b16 {%0,%1,%2,%3}, [%4];"
        : "=r"(r0), "=r"(r1), "=r"(r2), "=r"(r3) : "r"(addr));
}
__device__ __forceinline__ void cpasync16(uint32_t dst, uint64_t gsrc) {
    asm volatile("cp.async.cg.shared.global [%0], [%1], 16;" :: "r"(dst), "l"(gsrc) : "memory");
}
#define CP_COMMIT() asm volatile("cp.async.commit_group;" ::: "memory")
#define CP_WAIT2()  asm volatile("cp.async.wait_group 2;" ::: "memory")

// Smem tile: [128 rows][32 halves] = 64B/row = 4 16B-units/row.
// unit' = u ^ ((row>>1)&3)  -> cp.async stores and ldmatrix reads conflict-free.
// Stage = A tile (8KB) + B tile (8KB) = 16KB; 4 stages = 64KB dynamic smem.

// ---------------------------------------------------------------------------
// fp16 mma.sync GEMM (m16n8k16), K-major operands in gmem.
//   A: [M x K] half rows lda.  B: [N x K] half rows ldb (B^T effective).
//   outMode: 0 = float C (rowscale+bias+rowbias), 1 = half C (bias+rowbias),
//            2 = scoreExp: half C = exp(acc/8) diag-masked, partials -> lpart
//   BM=128, BN=128, BK=32, 256 thr, 4-stage cp.async pipeline.
// ---------------------------------------------------------------------------
__global__ __launch_bounds__(256, 2)
void mma_gemm(const __half* __restrict__ A, const __half* __restrict__ B,
              void* __restrict__ Cv, const float* __restrict__ bias,
              const float* __restrict__ rowbias,
              const float* __restrict__ rowscale, float* __restrict__ lpart,
              int N, int K, int lda, int ldb,
              int causalK, int causalSkip, int outMode,
              size_t sA, size_t sB, size_t sC, size_t sR)
{
    extern __shared__ uint32_t SM[];

    const int rb = blockIdx.y, cb = blockIdx.x, z = blockIdx.z;
    if (causalSkip && cb > rb) return;

    A += (size_t)z * sA;
    B += (size_t)z * sB;
    if (rowscale) rowscale += (size_t)z * sR;

    int kend = causalK ? (rb + 1) * 128 : K;
    if (kend > K) kend = K;
    const int NC = kend >> 5;

    const int tid = threadIdx.x, lane = tid & 31;
    const int wm = (tid >> 5) >> 1;      // 0..3
    const int wn = (tid >> 5) & 1;       // 0..1

    const __half* Ab = A + (size_t)rb * 128 * lda;
    const __half* Bb = B + (size_t)cb * 128 * ldb;
    uint64_t gAb, gBb;
    asm("cvta.to.global.u64 %0, %1;" : "=l"(gAb) : "l"(Ab));
    asm("cvta.to.global.u64 %0, %1;" : "=l"(gBb) : "l"(Bb));
    const uint32_t smb = (uint32_t)__cvta_generic_to_shared(SM);

    // cp.async slots: thread covers (row r, unit u) for A and B (2 each)
    uint32_t dstA[2], dstB[2];
    uint64_t offA[2], offB[2];
    #pragma unroll
    for (int it = 0; it < 2; it++) {
        int f = tid + it * 256;
        int r = f >> 2, u = f & 3;
        uint32_t sw = (uint32_t)(r * 64 + ((u ^ ((r >> 1) & 3)) << 4));
        dstA[it] = smb + sw;
        dstB[it] = smb + 8192u + sw;
        offA[it] = ((uint64_t)r * lda + (uint64_t)u * 8) * 2u;
        offB[it] = ((uint64_t)r * ldb + (uint64_t)u * 8) * 2u;
    }

    // ldmatrix addresses (stage 0); in-loop +stage*16384
    uint32_t adrA[2][2], adrB[4][2];
    {
        const int rl = ((lane >> 3) & 1) * 8 + (lane & 7);
        const int cl = (lane >> 4) & 1;
        #pragma unroll
        for (int mi = 0; mi < 2; mi++) {
            int r = wm * 32 + mi * 16 + rl;
            #pragma unroll
            for (int ks = 0; ks < 2; ks++) {
                int u = 2 * ks + cl;
                adrA[mi][ks] = smb + (uint32_t)(r * 64 + ((u ^ ((r >> 1) & 3)) << 4));
            }
        }
        #pragma unroll
        for (int p = 0; p < 4; p++) {
            int n = wn * 64 + p * 16 + rl;
            #pragma unroll
            for (int ks = 0; ks < 2; ks++) {
                int u = 2 * ks + cl;
                adrB[p][ks] = smb + 8192u + (uint32_t)(n * 64 + ((u ^ ((n >> 1) & 3)) << 4));
            }
        }
    }

    float acc[2][8][4];
    #pragma unroll
    for (int i = 0; i < 2; i++)
        #pragma unroll
        for (int j = 0; j < 8; j++)
            #pragma unroll
            for (int q = 0; q < 4; q++) acc[i][j][q] = 0.f;

    auto issue = [&](int c, int stg) {
        const uint32_t so = (uint32_t)stg * 16384u;
        const uint64_t co = (uint64_t)c * 64u;   // 32 halves along K
        #pragma unroll
        for (int it = 0; it < 2; it++)
            cpasync16(dstA[it] + so, gAb + co + offA[it]);
        #pragma unroll
        for (int it = 0; it < 2; it++)
            cpasync16(dstB[it] + so, gBb + co + offB[it]);
    };

    auto compute = [&](int stg) {
        const uint32_t bo = (uint32_t)stg * 16384u;
        #pragma unroll
        for (int ks = 0; ks < 2; ks++) {
            uint32_t a[2][4], b[8][2];
            #pragma unroll
            for (int mi = 0; mi < 2; mi++)
                ldsm4(a[mi][0], a[mi][1], a[mi][2], a[mi][3], adrA[mi][ks] + bo);
            #pragma unroll
            for (int p = 0; p < 4; p++)
                ldsm4(b[2 * p][0], b[2 * p + 1][0], b[2 * p][1], b[2 * p + 1][1],
                      adrB[p][ks] + bo);
            #pragma unroll
            for (int mi = 0; mi < 2; mi++)
                #pragma unroll
                for (int ni = 0; ni < 8; ni++)
                    mma_f16(acc[mi][ni], a[mi], b[ni]);
        }
    };

    #pragma unroll
    for (int s = 0; s < 3; s++) {
        if (s < NC) issue(s, s);
        CP_COMMIT();
    }
    for (int c = 0; c < NC; c++) {
        CP_WAIT2();
        __syncthreads();
        compute(c & 3);
        const int nc = c + 3;
        if (nc < NC) issue(nc, nc & 3);
        CP_COMMIT();
    }

    // ---------------- epilogue ----------------
    if (outMode == 2) {
        __half* C = (__half*)Cv + (size_t)z * sC;
        const bool diag = (cb == rb);
        float part[2][2] = {{0.f, 0.f}, {0.f, 0.f}};
        #pragma unroll
        for (int mi = 0; mi < 2; mi++) {
            int rbase = rb * 128 + wm * 32 + mi * 16 + (lane >> 2);
            #pragma unroll
            for (int half_ = 0; half_ < 2; half_++) {
                int row = rbase + half_ * 8;
                __half* Cp = C + (size_t)row * N;
                #pragma unroll
                for (int ni = 0; ni < 8; ni++) {
                    int col = cb * 128 + wn * 64 + ni * 8 + ((lane & 3) << 1);
                    float e0 = __expf(acc[mi][ni][half_ * 2 + 0] * 0.125f);
                    float e1 = __expf(acc[mi][ni][half_ * 2 + 1] * 0.125f);
                    if (diag) {
                        if (col > row) e0 = 0.f;
                        if (col + 1 > row) e1 = 0.f;
                    }
                    part[mi][half_] += e0 + e1;
                    *reinterpret_cast<__half2*>(Cp + col) = __floats2half2_rn(e0, e1);
                }
            }
        }
        __syncthreads();
        float* rs = reinterpret_cast<float*>(SM);   // [128][2]
        #pragma unroll
        for (int mi = 0; mi < 2; mi++)
            #pragma unroll
            for (int half_ = 0; half_ < 2; half_++) {
                float v = part[mi][half_];
                v += __shfl_xor_sync(0xFFFFFFFF, v, 1);
                v += __shfl_xor_sync(0xFFFFFFFF, v, 2);
                if ((lane & 3) == 0) {
                    int rl = wm * 32 + mi * 16 + half_ * 8 + (lane >> 2);
                    rs[rl * 2 + wn] = v;
                }
            }
        __syncthreads();
        if (tid < 128)
            lpart[(((size_t)z * SEQ) + rb * 128 + tid) * 16 + cb] =
                rs[tid * 2] + rs[tid * 2 + 1];
        return;
    }

    #pragma unroll
    for (int mi = 0; mi < 2; mi++) {
        int rbase = rb * 128 + wm * 32 + mi * 16 + (lane >> 2);
        #pragma unroll
        for (int half_ = 0; half_ < 2; half_++) {
            int row = rbase + half_ * 8;
            float sc = rowscale ? rowscale[row] : 1.0f;
            float rbv = rowbias ? rowbias[row] : 0.0f;
            #pragma unroll
            for (int ni = 0; ni < 8; ni++) {
                int col = cb * 128 + wn * 64 + ni * 8 + ((lane & 3) << 1);
                float b0 = rbv, b1 = rbv;
                if (bias) { b0 += bias[col]; b1 += bias[col + 1]; }
                float o0 = acc[mi][ni][half_ * 2 + 0] * sc + b0;
                float o1 = acc[mi][ni][half_ * 2 + 1] * sc + b1;
                if (outMode == 1) {
                    __half* Cp = (__half*)Cv + (size_t)z * sC + (size_t)row * N;
                    *reinterpret_cast<__half2*>(Cp + col) = __floats2half2_rn(o0, o1);
                } else {
                    float* Cp = (float*)Cv + (size_t)z * sC + (size_t)row * N;
                    *reinterpret_cast<float2*>(Cp + col) = make_float2(o0, o1);
                }
            }
        }
    }
}

// ---------------------------------------------------------------------------
// input fp32 -> fp16
__global__ void conv_half(const float4* __restrict__ in, __half2* __restrict__ out, int n4)
{
    int i = blockIdx.x * blockDim.x + threadIdx.x;
    if (i < n4) {
        float4 v = in[i];
        out[2 * i + 0] = __floats2half2_rn(v.x, v.y);
        out[2 * i + 1] = __floats2half2_rn(v.z, v.w);
    }
}

// 32x32 tiled transpose fp32 -> fp16: out[c][r] = half(in[r][c])
__global__ void transpose_half(const float* __restrict__ in, __half* __restrict__ out,
                               int R, int C)
{
    __shared__ float t[32][33];
    int c0 = blockIdx.x * 32, r0 = blockIdx.y * 32;
    int tx = threadIdx.x, ty = threadIdx.y;
    #pragma unroll
    for (int i = 0; i < 32; i += 8)
        t[ty + i][tx] = in[(size_t)(r0 + ty + i) * C + (c0 + tx)];
    __syncthreads();
    #pragma unroll
    for (int i = 0; i < 32; i += 8)
        out[(size_t)(c0 + ty + i) * R + (r0 + tx)] = __float2half_rn(t[tx][ty + i]);
}

__global__ void concat_bias(const float* __restrict__ bq, const float* __restrict__ bk,
                            float* __restrict__ o)
{
    int t = threadIdx.x;
    o[t] = (t < 64) ? bq[t] : bk[t - 64];
}

__global__ void linv_reduce(const float* __restrict__ lpart, float* __restrict__ linv)
{
    int i = blockIdx.x * blockDim.x + threadIdx.x;
    if (i < NB * SEQ) {
        int q = i & (SEQ - 1);
        int nb = (q >> 7) + 1;
        const float* p = lpart + (size_t)i * 16;
        float s = 0.f;
        for (int c = 0; c < nb; c++) s += p[c];
        linv[i] = 1.0f / s;
    }
}

// ---------------------------------------------------------------------------
extern "C" void kernel_launch(void* const* d_in, const int* in_sizes, int n_in,
                              void* d_out, int out_size)
{
    const float* input = (const float*)d_in[0];
    const float* Wq = (const float*)d_in[1];
    const float* bq = (const float*)d_in[2];
    const float* Wk = (const float*)d_in[3];
    const float* bk = (const float*)d_in[4];
    const float* Wv = (const float*)d_in[5];
    const float* bv = (const float*)d_in[6];
    float* out = (float*)d_out;

    __half *Xh, *QKh, *VTh, *Ph, *WqkTh, *WvTh;
    float *Lp, *L, *bqk;
    cudaGetSymbolAddress((void**)&Xh,    g_Xh);
    cudaGetSymbolAddress((void**)&QKh,   g_QKh);
    cudaGetSymbolAddress((void**)&VTh,   g_VTh);
    cudaGetSymbolAddress((void**)&Ph,    g_Ph);
    cudaGetSymbolAddress((void**)&Lp,    g_Lpart);
    cudaGetSymbolAddress((void**)&L,     g_Linv);
    cudaGetSymbolAddress((void**)&WqkTh, g_WqkTh);
    cudaGetSymbolAddress((void**)&WvTh,  g_WvTh);
    cudaGetSymbolAddress((void**)&bqk,   g_bqk);

    static int attrDone = 0;
    if (!attrDone) {
        cudaFuncSetAttribute(mma_gemm, cudaFuncAttributeMaxDynamicSharedMemorySize, 65536);
        attrDone = 1;
    }
    const int SMEMB = 65536;
    const int Mrows = NB * SEQ;   // 16384
    dim3 tb(32, 8);

    // pre-passes
    conv_half<<<Mrows * DM / 4 / 256, 256>>>(
        (const float4*)input, (__half2*)Xh, Mrows * DM / 4);
    transpose_half<<<dim3(2, 32), tb>>>(Wq, WqkTh, DM, DK);
    transpose_half<<<dim3(2, 32), tb>>>(Wk, WqkTh + 64 * DM, DM, DK);
    transpose_half<<<dim3(32, 32), tb>>>(Wv, WvTh, DM, DM);
    concat_bias<<<1, 128>>>(bq, bk, bqk);

    // QK = X @ [Wq|Wk] + [bq|bk]  -> half   [16384, 128]
    mma_gemm<<<dim3(1, Mrows / 128), 256, SMEMB>>>(
        Xh, WqkTh, QKh, bqk, nullptr, nullptr, nullptr,
        128, DM, DM, DM, 0, 0, 1, 0, 0, 0, 0);

    // VT = (X @ Wv + bv)^T  -> half  [DM, SEQ] per batch  (A=WvT, B=X, row bias)
    mma_gemm<<<dim3(SEQ / 128, DM / 128, NB), 256, SMEMB>>>(
        WvTh, Xh, VTh, nullptr, bv, nullptr, nullptr,
        SEQ, DM, DM, DM, 0, 0, 1,
        0, (size_t)SEQ * DM, (size_t)DM * SEQ, 0);

    // P = exp(Q@K^T / 8) diag-masked -> half; partials -> Lpart
    mma_gemm<<<dim3(SEQ / 128, SEQ / 128, NB), 256, SMEMB>>>(
        QKh, QKh + 64, Ph, nullptr, nullptr, nullptr, Lp,
        SEQ, DK, 128, 128, 0, 1, 2,
        (size_t)SEQ * 128, (size_t)SEQ * 128, (size_t)SEQ * SEQ, 0);

    // Linv = 1 / rowsum
    linv_reduce<<<Mrows / 256, 256>>>(Lp, L);

    // out = diag(Linv) * P @ V   (causal K-limit)   float out
    mma_gemm<<<dim3(DM / 128, SEQ / 128, NB), 256, SMEMB>>>(
        Ph, VTh, out, nullptr, nullptr, L, nullptr,
        DM, SEQ, SEQ, SEQ, 1, 0, 0,
        (size_t)SEQ * SEQ, (size_t)DM * SEQ, (size_t)SEQ * DM, (size_t)SEQ);
}